// round 2
// baseline (speedup 1.0000x reference)
#include <cuda_runtime.h>

#define B_SZ 512
#define I_SZ 256
#define H_SZ 512

// Scratch (no allocs allowed) — transformed params + per-h constants + state ping-pong
__device__ float g_SG[H_SZ*H_SZ];
__device__ float g_MS[H_SZ*H_SZ];
__device__ float g_WE[H_SZ*H_SZ];
__device__ float g_WW[H_SZ*H_SZ];
__device__ float g_CN[H_SZ];
__device__ float g_CD[H_SZ];
__device__ float g_A [B_SZ*H_SZ];   // gleak*vleak + CN + w_num_sensory
__device__ float g_Dc[B_SZ*H_SZ];   // cm + gleak + CD + w_den_sensory
__device__ float g_v0[B_SZ*H_SZ];
__device__ float g_v1[B_SZ*H_SZ];

__device__ __forceinline__ float tanh_fast(float x){
    float y;
    asm("tanh.approx.f32 %0, %1;" : "=f"(y) : "f"(x));
    return y;
}

// Transform recurrent params once per launch.
// sigmoid((v-mu)*sigma) = 0.5*tanh(0.5*sigma*v - 0.5*sigma*mu) + 0.5
__global__ void k_prep(const float* __restrict__ mu, const float* __restrict__ sigma,
                       const float* __restrict__ W,  const float* __restrict__ erev){
    int idx = blockIdx.x*blockDim.x + threadIdx.x;
    if (idx < H_SZ*H_SZ){
        float s = sigma[idx], m = mu[idx], w = W[idx], e = erev[idx];
        g_SG[idx] = 0.5f*s;
        g_MS[idx] = -0.5f*s*m;
        g_WE[idx] = 0.5f*w*e;
        g_WW[idx] = 0.5f*w;
    }
}

// Per-h column sums of WE/WW (the "+0.5" constant part of the recurrent sigmoid)
__global__ void k_colsum(){
    int h = blockIdx.x;
    int t = threadIdx.x;
    float sn = 0.f, sd = 0.f;
    for (int i = t; i < H_SZ; i += 128){
        sn += g_WE[i*H_SZ + h];
        sd += g_WW[i*H_SZ + h];
    }
    __shared__ float rn[128], rd[128];
    rn[t] = sn; rd[t] = sd;
    __syncthreads();
    for (int s = 64; s > 0; s >>= 1){
        if (t < s){ rn[t] += rn[t+s]; rd[t] += rd[t+s]; }
        __syncthreads();
    }
    if (t == 0){ g_CN[h] = rn[0]; g_CD[h] = rd[0]; }
}

// Sensory currents (once): A[b,h], Dc[b,h], with all per-launch constants folded in.
__global__ __launch_bounds__(128) void k_sensory(
        const float* __restrict__ inp,
        const float* __restrict__ smu, const float* __restrict__ ssig,
        const float* __restrict__ sW,  const float* __restrict__ serev,
        const float* __restrict__ vleak, const float* __restrict__ gleak,
        const float* __restrict__ cm){
    __shared__ float u_s[32][33];
    __shared__ float sg_s[32][32];
    __shared__ float ms_s[32][32];
    __shared__ float we_s[32][32];
    __shared__ float ww_s[32][32];

    const int h0 = blockIdx.x * 32;
    const int b0 = blockIdx.y * 32;
    const int tx = threadIdx.x;
    const int hq = tx & 15;       // thread covers h = h0 + 2*hq + {0,1}
    const int bq = tx >> 4;       // thread covers b = b0 + 4*bq + {0..3}

    float num[4][2] = {};
    float den[4][2] = {};

    for (int i0 = 0; i0 < I_SZ; i0 += 32){
        __syncthreads();
        #pragma unroll
        for (int k = 0; k < 8; k++){
            int idx = tx + k*128;
            int bb = idx >> 5, ic = idx & 31;
            u_s[bb][ic] = inp[(b0+bb)*I_SZ + i0 + ic];
        }
        #pragma unroll
        for (int k = 0; k < 8; k++){
            int idx = tx + k*128;
            int ic = idx >> 5, hh = idx & 31;
            int g = (i0+ic)*H_SZ + h0 + hh;
            float s = ssig[g], m = smu[g], w = sW[g], e = serev[g];
            sg_s[ic][hh] = 0.5f*s;
            ms_s[ic][hh] = -0.5f*s*m;
            we_s[ic][hh] = w*e;
            ww_s[ic][hh] = w;
        }
        __syncthreads();
        #pragma unroll 8
        for (int ic = 0; ic < 32; ic++){
            float2 sg = *(const float2*)&sg_s[ic][2*hq];
            float2 ms = *(const float2*)&ms_s[ic][2*hq];
            float2 we = *(const float2*)&we_s[ic][2*hq];
            float2 ww = *(const float2*)&ww_s[ic][2*hq];
            #pragma unroll
            for (int j = 0; j < 4; j++){
                float u = u_s[4*bq + j][ic];
                float t0 = tanh_fast(fmaf(u, sg.x, ms.x));
                float t1 = tanh_fast(fmaf(u, sg.y, ms.y));
                float a0 = fmaf(t0, 0.5f, 0.5f);
                float a1 = fmaf(t1, 0.5f, 0.5f);
                num[j][0] = fmaf(we.x, a0, num[j][0]);
                den[j][0] = fmaf(ww.x, a0, den[j][0]);
                num[j][1] = fmaf(we.y, a1, num[j][1]);
                den[j][1] = fmaf(ww.y, a1, den[j][1]);
            }
        }
    }

    #pragma unroll
    for (int k = 0; k < 2; k++){
        int h = h0 + 2*hq + k;
        float base_n = gleak[h]*vleak[h] + g_CN[h];
        float base_d = cm[h] + gleak[h] + g_CD[h];
        #pragma unroll
        for (int j = 0; j < 4; j++){
            int b = b0 + 4*bq + j;
            g_A [b*H_SZ + h] = num[j][k] + base_n;
            g_Dc[b*H_SZ + h] = den[j][k] + base_d;
        }
    }
}

// One recurrent unfold: vout = (cm*vin + A + sum_i WE*tanh) / (Dc + sum_i WW*tanh + 1e-8)
__global__ __launch_bounds__(128) void k_step(const float* vext, float* voutext,
                                              int sel_in, int sel_out,
                                              const float* __restrict__ cm){
    const float* vin  = (sel_in  == 0) ? g_v0 : ((sel_in  == 1) ? g_v1 : vext);
    float*       vout = (sel_out == 0) ? g_v0 : ((sel_out == 1) ? g_v1 : voutext);

    __shared__ float v_s[32][33];
    __shared__ float sg_s[32][32];
    __shared__ float ms_s[32][32];
    __shared__ float we_s[32][32];
    __shared__ float ww_s[32][32];

    const int h0 = blockIdx.x * 32;
    const int b0 = blockIdx.y * 32;
    const int tx = threadIdx.x;
    const int hq = tx & 15;
    const int bq = tx >> 4;

    float num[4][2] = {};
    float den[4][2] = {};

    for (int i0 = 0; i0 < H_SZ; i0 += 32){
        __syncthreads();
        #pragma unroll
        for (int k = 0; k < 8; k++){
            int idx = tx + k*128;
            int bb = idx >> 5, ic = idx & 31;
            v_s[bb][ic] = vin[(b0+bb)*H_SZ + i0 + ic];
        }
        #pragma unroll
        for (int k = 0; k < 8; k++){
            int idx = tx + k*128;
            int ic = idx >> 5, hh = idx & 31;
            int g = (i0+ic)*H_SZ + h0 + hh;
            sg_s[ic][hh] = g_SG[g];
            ms_s[ic][hh] = g_MS[g];
            we_s[ic][hh] = g_WE[g];
            ww_s[ic][hh] = g_WW[g];
        }
        __syncthreads();
        #pragma unroll 8
        for (int ic = 0; ic < 32; ic++){
            float2 sg = *(const float2*)&sg_s[ic][2*hq];
            float2 ms = *(const float2*)&ms_s[ic][2*hq];
            float2 we = *(const float2*)&we_s[ic][2*hq];
            float2 ww = *(const float2*)&ww_s[ic][2*hq];
            #pragma unroll
            for (int j = 0; j < 4; j++){
                float v = v_s[4*bq + j][ic];
                float t0 = tanh_fast(fmaf(v, sg.x, ms.x));
                float t1 = tanh_fast(fmaf(v, sg.y, ms.y));
                num[j][0] = fmaf(we.x, t0, num[j][0]);
                den[j][0] = fmaf(ww.x, t0, den[j][0]);
                num[j][1] = fmaf(we.y, t1, num[j][1]);
                den[j][1] = fmaf(ww.y, t1, den[j][1]);
            }
        }
    }

    #pragma unroll
    for (int k = 0; k < 2; k++){
        int h = h0 + 2*hq + k;
        float cmh = cm[h];
        #pragma unroll
        for (int j = 0; j < 4; j++){
            int b = b0 + 4*bq + j;
            float n = fmaf(cmh, vin[b*H_SZ + h], g_A[b*H_SZ + h]) + num[j][k];
            float d = g_Dc[b*H_SZ + h] + den[j][k];
            vout[b*H_SZ + h] = __fdividef(n, d + 1e-8f);
        }
    }
}

extern "C" void kernel_launch(void* const* d_in, const int* in_sizes, int n_in,
                              void* d_out, int out_size){
    const float* inputs = (const float*)d_in[0];
    const float* state  = (const float*)d_in[1];
    const float* smu    = (const float*)d_in[2];
    const float* ssig   = (const float*)d_in[3];
    const float* sW     = (const float*)d_in[4];
    const float* serev  = (const float*)d_in[5];
    const float* mu     = (const float*)d_in[6];
    const float* sigma  = (const float*)d_in[7];
    const float* W      = (const float*)d_in[8];
    const float* erev   = (const float*)d_in[9];
    const float* vleak  = (const float*)d_in[10];
    const float* gleak  = (const float*)d_in[11];
    const float* cm     = (const float*)d_in[12];
    float* out = (float*)d_out;

    k_prep<<<(H_SZ*H_SZ + 255)/256, 256>>>(mu, sigma, W, erev);
    k_colsum<<<H_SZ, 128>>>();

    dim3 grid(H_SZ/32, B_SZ/32);   // (16, 16)
    k_sensory<<<grid, 128>>>(inputs, smu, ssig, sW, serev, vleak, gleak, cm);

    // 6 unfolds: state -> v0 -> v1 -> v0 -> v1 -> v0 -> out
    k_step<<<grid, 128>>>(state,   nullptr, 2, 0, cm);
    k_step<<<grid, 128>>>(nullptr, nullptr, 0, 1, cm);
    k_step<<<grid, 128>>>(nullptr, nullptr, 1, 0, cm);
    k_step<<<grid, 128>>>(nullptr, nullptr, 0, 1, cm);
    k_step<<<grid, 128>>>(nullptr, nullptr, 1, 0, cm);
    k_step<<<grid, 128>>>(nullptr, out,     0, 2, cm);
}

// round 3
// speedup vs baseline: 1.5672x; 1.5672x over previous
#include <cuda_runtime.h>

#define B_SZ 512
#define I_SZ 256
#define H_SZ 512
#define ICH  32

// Scratch — transformed params + per-h constants + state ping-pong
__device__ float g_SG[H_SZ*H_SZ];
__device__ float g_MS[H_SZ*H_SZ];
__device__ float g_WE[H_SZ*H_SZ];
__device__ float g_WW[H_SZ*H_SZ];
__device__ float g_CN[H_SZ];
__device__ float g_CD[H_SZ];
__device__ float g_A [B_SZ*H_SZ];   // gleak*vleak + const(recur) + const(sens) + sensory num
__device__ float g_Dc[B_SZ*H_SZ];   // cm + gleak + consts + sensory den
__device__ float g_v0[B_SZ*H_SZ];
__device__ float g_v1[B_SZ*H_SZ];

__device__ __forceinline__ float tanh_fast(float x){
    float y;
    asm("tanh.approx.f32 %0, %1;" : "=f"(y) : "f"(x));
    return y;
}

// sigmoid((v-mu)*sigma) = 0.5*tanh(0.5*sigma*v - 0.5*sigma*mu) + 0.5
// contribution to num: W*erev*sig = (0.5*W*erev)*tanh + 0.5*W*erev
//                 den: W*sig      = (0.5*W)*tanh      + 0.5*W
__global__ void k_prep(const float* __restrict__ mu, const float* __restrict__ sigma,
                       const float* __restrict__ W,  const float* __restrict__ erev){
    int idx = blockIdx.x*blockDim.x + threadIdx.x;
    if (idx < H_SZ*H_SZ){
        float s = sigma[idx], m = mu[idx], w = W[idx], e = erev[idx];
        g_SG[idx] = 0.5f*s;
        g_MS[idx] = -0.5f*s*m;
        g_WE[idx] = 0.5f*w*e;
        g_WW[idx] = 0.5f*w;
    }
}

// Per-h constants: recurrent col-sums of g_WE/g_WW  +  sensory 0.5*sum(W*erev), 0.5*sum(W)
__global__ void k_colsum(const float* __restrict__ sW, const float* __restrict__ serev){
    int h0 = blockIdx.x * 32;
    int hh = threadIdx.x & 31;
    int it = threadIdx.x >> 5;          // 8 slices
    float sn = 0.f, sd = 0.f;
    for (int i = it; i < H_SZ; i += 8){
        sn += g_WE[i*H_SZ + h0 + hh];
        sd += g_WW[i*H_SZ + h0 + hh];
    }
    for (int i = it; i < I_SZ; i += 8){
        float w = sW[i*H_SZ + h0 + hh], e = serev[i*H_SZ + h0 + hh];
        sn = fmaf(0.5f*w, e, sn);
        sd += 0.5f*w;
    }
    __shared__ float rn[8][32], rd[8][32];
    rn[it][hh] = sn; rd[it][hh] = sd;
    __syncthreads();
    if (it == 0){
        float a = 0.f, b = 0.f;
        #pragma unroll
        for (int k = 0; k < 8; k++){ a += rn[k][hh]; b += rd[k][hh]; }
        g_CN[h0+hh] = a; g_CD[h0+hh] = b;
    }
}

// ---------------------------------------------------------------------------
// Sensory pass: A[b,h], Dc[b,h]. Tile 16b x 32h, 128 threads, double-buffered.
// ---------------------------------------------------------------------------
__global__ __launch_bounds__(128) void k_sensory(
        const float* __restrict__ inp,
        const float* __restrict__ smu, const float* __restrict__ ssig,
        const float* __restrict__ sW,  const float* __restrict__ serev,
        const float* __restrict__ vleak, const float* __restrict__ gleak,
        const float* __restrict__ cm){
    __shared__ __align__(16) float sg[2][ICH][32];
    __shared__ __align__(16) float ms[2][ICH][32];
    __shared__ __align__(16) float we[2][ICH][32];
    __shared__ __align__(16) float ww[2][ICH][32];
    __shared__ float vs[2][16][33];

    const int h0 = blockIdx.x * 32;
    const int b0 = blockIdx.y * 16;
    const int tx = threadIdx.x;
    const int hq = tx & 15;     // h = h0 + 2*hq + {0,1}
    const int bq = tx >> 4;     // b = b0 + 2*bq + {0,1}
    const int vrow = tx >> 3, vq = (tx & 7) * 4;

    float4 pSG[2], pMS[2], pWE[2], pWW[2], pV;

    auto prefetch = [&](int c){
        int i0 = c * ICH;
        #pragma unroll
        for (int r = 0; r < 2; r++){
            int s = tx + r*128;
            int ic = s >> 3, q = (s & 7) * 4;
            int g = (i0 + ic)*H_SZ + h0 + q;
            float4 sg4 = *(const float4*)&ssig[g];
            float4 mu4 = *(const float4*)&smu[g];
            float4 w4  = *(const float4*)&sW[g];
            float4 e4  = *(const float4*)&serev[g];
            pSG[r] = make_float4(0.5f*sg4.x, 0.5f*sg4.y, 0.5f*sg4.z, 0.5f*sg4.w);
            pMS[r] = make_float4(-0.5f*sg4.x*mu4.x, -0.5f*sg4.y*mu4.y,
                                 -0.5f*sg4.z*mu4.z, -0.5f*sg4.w*mu4.w);
            pWE[r] = make_float4(0.5f*w4.x*e4.x, 0.5f*w4.y*e4.y,
                                 0.5f*w4.z*e4.z, 0.5f*w4.w*e4.w);
            pWW[r] = make_float4(0.5f*w4.x, 0.5f*w4.y, 0.5f*w4.z, 0.5f*w4.w);
        }
        pV = *(const float4*)&inp[(b0 + vrow)*I_SZ + i0 + vq];
    };
    auto sts = [&](int buf){
        #pragma unroll
        for (int r = 0; r < 2; r++){
            int s = tx + r*128;
            int ic = s >> 3, q = (s & 7) * 4;
            *(float4*)&sg[buf][ic][q] = pSG[r];
            *(float4*)&ms[buf][ic][q] = pMS[r];
            *(float4*)&we[buf][ic][q] = pWE[r];
            *(float4*)&ww[buf][ic][q] = pWW[r];
        }
        vs[buf][vrow][vq+0] = pV.x; vs[buf][vrow][vq+1] = pV.y;
        vs[buf][vrow][vq+2] = pV.z; vs[buf][vrow][vq+3] = pV.w;
    };

    float num[2][2] = {}, den[2][2] = {};
    const int NC = I_SZ / ICH;   // 8
    int buf = 0;
    prefetch(0); sts(0); __syncthreads();

    for (int c = 0; c < NC; c++){
        if (c + 1 < NC) prefetch(c + 1);
        #pragma unroll 8
        for (int ic = 0; ic < ICH; ic++){
            float2 SG = *(const float2*)&sg[buf][ic][2*hq];
            float2 MS = *(const float2*)&ms[buf][ic][2*hq];
            float2 WE = *(const float2*)&we[buf][ic][2*hq];
            float2 WW = *(const float2*)&ww[buf][ic][2*hq];
            float va = vs[buf][2*bq+0][ic];
            float vb = vs[buf][2*bq+1][ic];
            float t00 = tanh_fast(fmaf(va, SG.x, MS.x));
            float t01 = tanh_fast(fmaf(va, SG.y, MS.y));
            float t10 = tanh_fast(fmaf(vb, SG.x, MS.x));
            float t11 = tanh_fast(fmaf(vb, SG.y, MS.y));
            num[0][0] = fmaf(WE.x, t00, num[0][0]); den[0][0] = fmaf(WW.x, t00, den[0][0]);
            num[0][1] = fmaf(WE.y, t01, num[0][1]); den[0][1] = fmaf(WW.y, t01, den[0][1]);
            num[1][0] = fmaf(WE.x, t10, num[1][0]); den[1][0] = fmaf(WW.x, t10, den[1][0]);
            num[1][1] = fmaf(WE.y, t11, num[1][1]); den[1][1] = fmaf(WW.y, t11, den[1][1]);
        }
        if (c + 1 < NC){ sts(buf ^ 1); __syncthreads(); buf ^= 1; }
    }

    #pragma unroll
    for (int k = 0; k < 2; k++){
        int h = h0 + 2*hq + k;
        float base_n = fmaf(gleak[h], vleak[h], g_CN[h]);
        float base_d = cm[h] + gleak[h] + g_CD[h];
        #pragma unroll
        for (int j = 0; j < 2; j++){
            int b = b0 + 2*bq + j;
            g_A [b*H_SZ + h] = num[j][k] + base_n;
            g_Dc[b*H_SZ + h] = den[j][k] + base_d;
        }
    }
}

// ---------------------------------------------------------------------------
// One recurrent unfold. Tile 16b x 32h, 128 threads, double-buffered SMEM.
// ---------------------------------------------------------------------------
__global__ __launch_bounds__(128) void k_step(const float* vext, float* voutext,
                                              int sel_in, int sel_out,
                                              const float* __restrict__ cm){
    const float* vin  = (sel_in  == 0) ? g_v0 : ((sel_in  == 1) ? g_v1 : vext);
    float*       vout = (sel_out == 0) ? g_v0 : ((sel_out == 1) ? g_v1 : voutext);

    __shared__ __align__(16) float sg[2][ICH][32];
    __shared__ __align__(16) float ms[2][ICH][32];
    __shared__ __align__(16) float we[2][ICH][32];
    __shared__ __align__(16) float ww[2][ICH][32];
    __shared__ float vs[2][16][33];

    const int h0 = blockIdx.x * 32;
    const int b0 = blockIdx.y * 16;
    const int tx = threadIdx.x;
    const int hq = tx & 15;
    const int bq = tx >> 4;
    const int vrow = tx >> 3, vq = (tx & 7) * 4;

    float4 pSG[2], pMS[2], pWE[2], pWW[2], pV;

    auto prefetch = [&](int c){
        int i0 = c * ICH;
        #pragma unroll
        for (int r = 0; r < 2; r++){
            int s = tx + r*128;
            int ic = s >> 3, q = (s & 7) * 4;
            int g = (i0 + ic)*H_SZ + h0 + q;
            pSG[r] = *(const float4*)&g_SG[g];
            pMS[r] = *(const float4*)&g_MS[g];
            pWE[r] = *(const float4*)&g_WE[g];
            pWW[r] = *(const float4*)&g_WW[g];
        }
        pV = *(const float4*)&vin[(b0 + vrow)*H_SZ + i0 + vq];
    };
    auto sts = [&](int buf){
        #pragma unroll
        for (int r = 0; r < 2; r++){
            int s = tx + r*128;
            int ic = s >> 3, q = (s & 7) * 4;
            *(float4*)&sg[buf][ic][q] = pSG[r];
            *(float4*)&ms[buf][ic][q] = pMS[r];
            *(float4*)&we[buf][ic][q] = pWE[r];
            *(float4*)&ww[buf][ic][q] = pWW[r];
        }
        vs[buf][vrow][vq+0] = pV.x; vs[buf][vrow][vq+1] = pV.y;
        vs[buf][vrow][vq+2] = pV.z; vs[buf][vrow][vq+3] = pV.w;
    };

    float num[2][2] = {}, den[2][2] = {};
    const int NC = H_SZ / ICH;   // 16
    int buf = 0;
    prefetch(0); sts(0); __syncthreads();

    for (int c = 0; c < NC; c++){
        if (c + 1 < NC) prefetch(c + 1);
        #pragma unroll 8
        for (int ic = 0; ic < ICH; ic++){
            float2 SG = *(const float2*)&sg[buf][ic][2*hq];
            float2 MS = *(const float2*)&ms[buf][ic][2*hq];
            float2 WE = *(const float2*)&we[buf][ic][2*hq];
            float2 WW = *(const float2*)&ww[buf][ic][2*hq];
            float va = vs[buf][2*bq+0][ic];
            float vb = vs[buf][2*bq+1][ic];
            float t00 = tanh_fast(fmaf(va, SG.x, MS.x));
            float t01 = tanh_fast(fmaf(va, SG.y, MS.y));
            float t10 = tanh_fast(fmaf(vb, SG.x, MS.x));
            float t11 = tanh_fast(fmaf(vb, SG.y, MS.y));
            num[0][0] = fmaf(WE.x, t00, num[0][0]); den[0][0] = fmaf(WW.x, t00, den[0][0]);
            num[0][1] = fmaf(WE.y, t01, num[0][1]); den[0][1] = fmaf(WW.y, t01, den[0][1]);
            num[1][0] = fmaf(WE.x, t10, num[1][0]); den[1][0] = fmaf(WW.x, t10, den[1][0]);
            num[1][1] = fmaf(WE.y, t11, num[1][1]); den[1][1] = fmaf(WW.y, t11, den[1][1]);
        }
        if (c + 1 < NC){ sts(buf ^ 1); __syncthreads(); buf ^= 1; }
    }

    #pragma unroll
    for (int k = 0; k < 2; k++){
        int h = h0 + 2*hq + k;
        float cmh = cm[h];
        #pragma unroll
        for (int j = 0; j < 2; j++){
            int b = b0 + 2*bq + j;
            float n = fmaf(cmh, vin[b*H_SZ + h], g_A[b*H_SZ + h]) + num[j][k];
            float d = g_Dc[b*H_SZ + h] + den[j][k];
            vout[b*H_SZ + h] = __fdividef(n, d + 1e-8f);
        }
    }
}

extern "C" void kernel_launch(void* const* d_in, const int* in_sizes, int n_in,
                              void* d_out, int out_size){
    const float* inputs = (const float*)d_in[0];
    const float* state  = (const float*)d_in[1];
    const float* smu    = (const float*)d_in[2];
    const float* ssig   = (const float*)d_in[3];
    const float* sW     = (const float*)d_in[4];
    const float* serev  = (const float*)d_in[5];
    const float* mu     = (const float*)d_in[6];
    const float* sigma  = (const float*)d_in[7];
    const float* W      = (const float*)d_in[8];
    const float* erev   = (const float*)d_in[9];
    const float* vleak  = (const float*)d_in[10];
    const float* gleak  = (const float*)d_in[11];
    const float* cm     = (const float*)d_in[12];
    float* out = (float*)d_out;

    k_prep<<<(H_SZ*H_SZ + 255)/256, 256>>>(mu, sigma, W, erev);
    k_colsum<<<H_SZ/32, 256>>>(sW, serev);

    dim3 grid(H_SZ/32, B_SZ/16);   // (16, 32) = 512 blocks
    k_sensory<<<grid, 128>>>(inputs, smu, ssig, sW, serev, vleak, gleak, cm);

    // 6 unfolds: state -> v0 -> v1 -> v0 -> v1 -> v0 -> out
    k_step<<<grid, 128>>>(state,   nullptr, 2, 0, cm);
    k_step<<<grid, 128>>>(nullptr, nullptr, 0, 1, cm);
    k_step<<<grid, 128>>>(nullptr, nullptr, 1, 0, cm);
    k_step<<<grid, 128>>>(nullptr, nullptr, 0, 1, cm);
    k_step<<<grid, 128>>>(nullptr, nullptr, 1, 0, cm);
    k_step<<<grid, 128>>>(nullptr, out,     0, 2, cm);
}

// round 4
// speedup vs baseline: 1.6597x; 1.0590x over previous
#include <cuda_runtime.h>
#include <cstdint>

#define B_SZ 512
#define I_SZ 256
#define H_SZ 512
#define ICH  16

// Transformed parameter planes (recurrent + sensory) and scratch
__device__ float g_SG[H_SZ*H_SZ];
__device__ float g_MS[H_SZ*H_SZ];
__device__ float g_WE[H_SZ*H_SZ];
__device__ float g_WW[H_SZ*H_SZ];
__device__ float s_SG[I_SZ*H_SZ];
__device__ float s_MS[I_SZ*H_SZ];
__device__ float s_WE[I_SZ*H_SZ];
__device__ float s_WW[I_SZ*H_SZ];
__device__ float g_CN[H_SZ];
__device__ float g_CD[H_SZ];
__device__ float g_A [B_SZ*H_SZ];
__device__ float g_Dc[B_SZ*H_SZ];
__device__ float g_v0[B_SZ*H_SZ];
__device__ float g_v1[B_SZ*H_SZ];

__device__ __forceinline__ float tanh_fast(float x){
    float y;
    asm("tanh.approx.f32 %0, %1;" : "=f"(y) : "f"(x));
    return y;
}

// sigmoid((v-mu)*sigma) = 0.5*tanh(0.5*sigma*v - 0.5*sigma*mu) + 0.5
// num contrib: (0.5*W*erev)*tanh + 0.5*W*erev ; den: (0.5*W)*tanh + 0.5*W
__global__ void k_prep(const float* __restrict__ mu, const float* __restrict__ sigma,
                       const float* __restrict__ W,  const float* __restrict__ erev,
                       const float* __restrict__ smu, const float* __restrict__ ssig,
                       const float* __restrict__ sW,  const float* __restrict__ serev){
    int idx = blockIdx.x*blockDim.x + threadIdx.x;
    if (idx < H_SZ*H_SZ){
        float s = sigma[idx], m = mu[idx], w = W[idx], e = erev[idx];
        g_SG[idx] = 0.5f*s;
        g_MS[idx] = -0.5f*s*m;
        g_WE[idx] = 0.5f*w*e;
        g_WW[idx] = 0.5f*w;
    } else if (idx < (H_SZ + I_SZ)*H_SZ){
        int j = idx - H_SZ*H_SZ;
        float s = ssig[j], m = smu[j], w = sW[j], e = serev[j];
        s_SG[j] = 0.5f*s;
        s_MS[j] = -0.5f*s*m;
        s_WE[j] = 0.5f*w*e;
        s_WW[j] = 0.5f*w;
    }
}

// Per-h constants: column sums of WE/WW over recurrent (H) + sensory (I) rows
__global__ void k_colsum(){
    int h0 = blockIdx.x * 32;
    int hh = threadIdx.x & 31;
    int it = threadIdx.x >> 5;          // 8 slices
    float sn = 0.f, sd = 0.f;
    for (int i = it; i < H_SZ; i += 8){
        sn += g_WE[i*H_SZ + h0 + hh];
        sd += g_WW[i*H_SZ + h0 + hh];
    }
    for (int i = it; i < I_SZ; i += 8){
        sn += s_WE[i*H_SZ + h0 + hh];
        sd += s_WW[i*H_SZ + h0 + hh];
    }
    __shared__ float rn[8][32], rd[8][32];
    rn[it][hh] = sn; rd[it][hh] = sd;
    __syncthreads();
    if (it == 0){
        float a = 0.f, b = 0.f;
        #pragma unroll
        for (int k = 0; k < 8; k++){ a += rn[k][hh]; b += rd[k][hh]; }
        g_CN[h0+hh] = a; g_CD[h0+hh] = b;
    }
}

// ---------------------------------------------------------------------------
// Main loop core. Tile: 64 h (h = h0 + 2*lane + {0,1}) x 16 b (b-quad per warp).
// 128 threads. Params: warp reads 32 distinct float2 per LDS.64 -> 2 wf, no waste.
// v: broadcast LDS.32. Register double-buffer, 1 barrier per chunk.
// ---------------------------------------------------------------------------
template<int NC, int VSTR>
__device__ __forceinline__ void mainloop_core(
        const float* __restrict__ P0, const float* __restrict__ P1,
        const float* __restrict__ P2, const float* __restrict__ P3,
        const float* __restrict__ vin, int h0, int b0, int tx,
        float (&num)[4][2], float (&den)[4][2],
        float (*sp)[4][ICH][64], float (*vs)[16][ICH+1])
{
    const int lane = tx & 31;
    const int w    = tx >> 5;
    const int vrow = tx >> 3;          // 0..15
    const int vq   = (tx & 7) * 2;     // 0..14

    float4 r[8];
    float2 rv;

    auto prefetch = [&](int c){
        int i0 = c * ICH;
        #pragma unroll
        for (int k = 0; k < 8; k++){
            const float* base = (k < 2) ? P0 : (k < 4) ? P1 : (k < 6) ? P2 : P3;
            int rem = tx + (k & 1) * 128;      // 0..255
            int ic  = rem >> 4;                // 0..15
            int q   = (rem & 15) * 4;          // 0..60
            r[k] = *(const float4*)&base[(i0 + ic)*H_SZ + h0 + q];
        }
        rv = *(const float2*)&vin[(b0 + vrow)*VSTR + i0 + vq];
    };
    auto sts = [&](int buf){
        #pragma unroll
        for (int k = 0; k < 8; k++){
            int a   = k >> 1;
            int rem = tx + (k & 1) * 128;
            int ic  = rem >> 4;
            int q   = (rem & 15) * 4;
            *(float4*)&sp[buf][a][ic][q] = r[k];
        }
        vs[buf][vrow][vq+0] = rv.x;
        vs[buf][vrow][vq+1] = rv.y;
    };

    int buf = 0;
    prefetch(0); sts(0); __syncthreads();

    for (int c = 0; c < NC; c++){
        if (c + 1 < NC) prefetch(c + 1);
        #pragma unroll
        for (int ic = 0; ic < ICH; ic++){
            float2 SG = *(const float2*)&sp[buf][0][ic][2*lane];
            float2 MS = *(const float2*)&sp[buf][1][ic][2*lane];
            float2 WE = *(const float2*)&sp[buf][2][ic][2*lane];
            float2 WW = *(const float2*)&sp[buf][3][ic][2*lane];
            #pragma unroll
            for (int j = 0; j < 4; j++){
                float v = vs[buf][4*w + j][ic];
                float t0 = tanh_fast(fmaf(v, SG.x, MS.x));
                float t1 = tanh_fast(fmaf(v, SG.y, MS.y));
                num[j][0] = fmaf(WE.x, t0, num[j][0]);
                den[j][0] = fmaf(WW.x, t0, den[j][0]);
                num[j][1] = fmaf(WE.y, t1, num[j][1]);
                den[j][1] = fmaf(WW.y, t1, den[j][1]);
            }
        }
        if (c + 1 < NC){ sts(buf ^ 1); __syncthreads(); buf ^= 1; }
    }
}

// ---------------------------------------------------------------------------
// Sensory pass: writes A[b,h], Dc[b,h] with all constants folded in.
// ---------------------------------------------------------------------------
__global__ __launch_bounds__(128) void k_sensory(
        const float* __restrict__ inp,
        const float* __restrict__ vleak, const float* __restrict__ gleak,
        const float* __restrict__ cm){
    __shared__ __align__(16) float sp[2][4][ICH][64];
    __shared__ float vs[2][16][ICH+1];

    const int h0 = blockIdx.x * 64;
    const int b0 = blockIdx.y * 16;
    const int tx = threadIdx.x;
    const int lane = tx & 31;
    const int w    = tx >> 5;

    float num[4][2] = {}, den[4][2] = {};
    mainloop_core<I_SZ/ICH, I_SZ>(s_SG, s_MS, s_WE, s_WW, inp, h0, b0, tx,
                                  num, den, sp, vs);

    #pragma unroll
    for (int k = 0; k < 2; k++){
        int h = h0 + 2*lane + k;
        float base_n = fmaf(gleak[h], vleak[h], g_CN[h]);
        float base_d = cm[h] + gleak[h] + g_CD[h];
        #pragma unroll
        for (int j = 0; j < 4; j++){
            int b = b0 + 4*w + j;
            g_A [b*H_SZ + h] = num[j][k] + base_n;
            g_Dc[b*H_SZ + h] = den[j][k] + base_d;
        }
    }
}

// ---------------------------------------------------------------------------
// One recurrent unfold.
// ---------------------------------------------------------------------------
__global__ __launch_bounds__(128) void k_step(const float* vext, float* voutext,
                                              int sel_in, int sel_out,
                                              const float* __restrict__ cm){
    const float* vin  = (sel_in  == 0) ? g_v0 : ((sel_in  == 1) ? g_v1 : vext);
    float*       vout = (sel_out == 0) ? g_v0 : ((sel_out == 1) ? g_v1 : voutext);

    __shared__ __align__(16) float sp[2][4][ICH][64];
    __shared__ float vs[2][16][ICH+1];

    const int h0 = blockIdx.x * 64;
    const int b0 = blockIdx.y * 16;
    const int tx = threadIdx.x;
    const int lane = tx & 31;
    const int w    = tx >> 5;

    float num[4][2] = {}, den[4][2] = {};
    mainloop_core<H_SZ/ICH, H_SZ>(g_SG, g_MS, g_WE, g_WW, vin, h0, b0, tx,
                                  num, den, sp, vs);

    #pragma unroll
    for (int k = 0; k < 2; k++){
        int h = h0 + 2*lane + k;
        float cmh = cm[h];
        #pragma unroll
        for (int j = 0; j < 4; j++){
            int b = b0 + 4*w + j;
            float n = fmaf(cmh, vin[b*H_SZ + h], g_A[b*H_SZ + h]) + num[j][k];
            float d = g_Dc[b*H_SZ + h] + den[j][k];
            vout[b*H_SZ + h] = __fdividef(n, d + 1e-8f);
        }
    }
}

extern "C" void kernel_launch(void* const* d_in, const int* in_sizes, int n_in,
                              void* d_out, int out_size){
    const float* inputs = (const float*)d_in[0];
    const float* state  = (const float*)d_in[1];
    const float* smu    = (const float*)d_in[2];
    const float* ssig   = (const float*)d_in[3];
    const float* sW     = (const float*)d_in[4];
    const float* serev  = (const float*)d_in[5];
    const float* mu     = (const float*)d_in[6];
    const float* sigma  = (const float*)d_in[7];
    const float* W      = (const float*)d_in[8];
    const float* erev   = (const float*)d_in[9];
    const float* vleak  = (const float*)d_in[10];
    const float* gleak  = (const float*)d_in[11];
    const float* cm     = (const float*)d_in[12];
    float* out = (float*)d_out;

    k_prep<<<((H_SZ+I_SZ)*H_SZ + 255)/256, 256>>>(mu, sigma, W, erev,
                                                  smu, ssig, sW, serev);
    k_colsum<<<H_SZ/32, 256>>>();

    dim3 grid(H_SZ/64, B_SZ/16);   // (8, 32) = 256 blocks
    k_sensory<<<grid, 128>>>(inputs, vleak, gleak, cm);

    // 6 unfolds: state -> v0 -> v1 -> v0 -> v1 -> v0 -> out
    k_step<<<grid, 128>>>(state,   nullptr, 2, 0, cm);
    k_step<<<grid, 128>>>(nullptr, nullptr, 0, 1, cm);
    k_step<<<grid, 128>>>(nullptr, nullptr, 1, 0, cm);
    k_step<<<grid, 128>>>(nullptr, nullptr, 0, 1, cm);
    k_step<<<grid, 128>>>(nullptr, nullptr, 1, 0, cm);
    k_step<<<grid, 128>>>(nullptr, out,     0, 2, cm);
}

// round 5
// speedup vs baseline: 1.8964x; 1.1426x over previous
#include <cuda_runtime.h>
#include <cstdint>

#define B_SZ 512
#define I_SZ 256
#define H_SZ 512
#define ICH  8

// Transformed parameter planes (recurrent + sensory) and scratch
__device__ float g_SG[H_SZ*H_SZ];
__device__ float g_MS[H_SZ*H_SZ];
__device__ float g_WE[H_SZ*H_SZ];
__device__ float g_WW[H_SZ*H_SZ];
__device__ float s_SG[I_SZ*H_SZ];
__device__ float s_MS[I_SZ*H_SZ];
__device__ float s_WE[I_SZ*H_SZ];
__device__ float s_WW[I_SZ*H_SZ];
__device__ float g_CN[H_SZ];
__device__ float g_CD[H_SZ];
__device__ float g_A [B_SZ*H_SZ];
__device__ float g_Dc[B_SZ*H_SZ];
__device__ float g_v0[B_SZ*H_SZ];
__device__ float g_v1[B_SZ*H_SZ];

__device__ __forceinline__ float tanh_fast(float x){
    float y;
    asm("tanh.approx.f32 %0, %1;" : "=f"(y) : "f"(x));
    return y;
}

// sigmoid((v-mu)*sigma) = 0.5*tanh(0.5*sigma*v - 0.5*sigma*mu) + 0.5
__global__ void k_prep(const float* __restrict__ mu, const float* __restrict__ sigma,
                       const float* __restrict__ W,  const float* __restrict__ erev,
                       const float* __restrict__ smu, const float* __restrict__ ssig,
                       const float* __restrict__ sW,  const float* __restrict__ serev){
    int idx = blockIdx.x*blockDim.x + threadIdx.x;
    if (idx < H_SZ*H_SZ){
        float s = sigma[idx], m = mu[idx], w = W[idx], e = erev[idx];
        g_SG[idx] = 0.5f*s;
        g_MS[idx] = -0.5f*s*m;
        g_WE[idx] = 0.5f*w*e;
        g_WW[idx] = 0.5f*w;
    } else if (idx < (H_SZ + I_SZ)*H_SZ){
        int j = idx - H_SZ*H_SZ;
        float s = ssig[j], m = smu[j], w = sW[j], e = serev[j];
        s_SG[j] = 0.5f*s;
        s_MS[j] = -0.5f*s*m;
        s_WE[j] = 0.5f*w*e;
        s_WW[j] = 0.5f*w;
    }
}

// Per-h constants: column sums of WE/WW over recurrent (H) + sensory (I) rows
__global__ void k_colsum(){
    int h0 = blockIdx.x * 32;
    int hh = threadIdx.x & 31;
    int it = threadIdx.x >> 5;
    float sn = 0.f, sd = 0.f;
    for (int i = it; i < H_SZ; i += 8){
        sn += g_WE[i*H_SZ + h0 + hh];
        sd += g_WW[i*H_SZ + h0 + hh];
    }
    for (int i = it; i < I_SZ; i += 8){
        sn += s_WE[i*H_SZ + h0 + hh];
        sd += s_WW[i*H_SZ + h0 + hh];
    }
    __shared__ float rn[8][32], rd[8][32];
    rn[it][hh] = sn; rd[it][hh] = sd;
    __syncthreads();
    if (it == 0){
        float a = 0.f, b = 0.f;
        #pragma unroll
        for (int k = 0; k < 8; k++){ a += rn[k][hh]; b += rd[k][hh]; }
        g_CN[h0+hh] = a; g_CD[h0+hh] = b;
    }
}

// ---------------------------------------------------------------------------
// Main loop core, i-split within block.
// 256 threads = 2 halves x 4 warps. Tile 64h x 16b. Half hf reduces
// i in [hf*HALF_I, (hf+1)*HALF_I). Lane covers h = h0+2*lane+{0,1} (64 distinct
// floats per param LDS.64 -> conflict-free). Warp-in-half covers 4 batches.
// Register double-buffer, one joint barrier per chunk.
// ---------------------------------------------------------------------------
template<int HALF_I, int VSTR>
__device__ __forceinline__ void mainloop_core(
        const float* __restrict__ P0, const float* __restrict__ P1,
        const float* __restrict__ P2, const float* __restrict__ P3,
        const float* __restrict__ vin, int h0, int b0, int tx,
        float (&num)[4][2], float (&den)[4][2],
        float (*sp)[2][4][ICH][64], float (*vs)[2][16][ICH+1])
{
    const int hf   = tx >> 7;          // half: 0/1
    const int txh  = tx & 127;
    const int lane = tx & 31;
    const int wq   = (txh >> 5);       // warp in half: 0..3
    const int ibase = hf * HALF_I;
    const int pic  = txh >> 4;         // 0..7   (prefetch ic)
    const int pq   = (txh & 15) * 4;   // 0..60  (prefetch h-quad)
    const int vrow = txh >> 3;         // 0..15
    const int vq   = txh & 7;          // 0..7
    const int NC   = HALF_I / ICH;

    float4 r[4];
    float rv;

    auto prefetch = [&](int c){
        int i0 = ibase + c * ICH;
        int g  = (i0 + pic)*H_SZ + h0 + pq;
        r[0] = *(const float4*)&P0[g];
        r[1] = *(const float4*)&P1[g];
        r[2] = *(const float4*)&P2[g];
        r[3] = *(const float4*)&P3[g];
        rv   = vin[(b0 + vrow)*VSTR + i0 + vq];
    };
    auto sts = [&](int buf){
        *(float4*)&sp[hf][buf][0][pic][pq] = r[0];
        *(float4*)&sp[hf][buf][1][pic][pq] = r[1];
        *(float4*)&sp[hf][buf][2][pic][pq] = r[2];
        *(float4*)&sp[hf][buf][3][pic][pq] = r[3];
        vs[hf][buf][vrow][vq] = rv;
    };

    int buf = 0;
    prefetch(0); sts(0); __syncthreads();

    for (int c = 0; c < NC; c++){
        if (c + 1 < NC) prefetch(c + 1);
        #pragma unroll
        for (int ic = 0; ic < ICH; ic++){
            float2 SG = *(const float2*)&sp[hf][buf][0][ic][2*lane];
            float2 MS = *(const float2*)&sp[hf][buf][1][ic][2*lane];
            float2 WE = *(const float2*)&sp[hf][buf][2][ic][2*lane];
            float2 WW = *(const float2*)&sp[hf][buf][3][ic][2*lane];
            #pragma unroll
            for (int j = 0; j < 4; j++){
                float v = vs[hf][buf][4*wq + j][ic];
                float t0 = tanh_fast(fmaf(v, SG.x, MS.x));
                float t1 = tanh_fast(fmaf(v, SG.y, MS.y));
                num[j][0] = fmaf(WE.x, t0, num[j][0]);
                den[j][0] = fmaf(WW.x, t0, den[j][0]);
                num[j][1] = fmaf(WE.y, t1, num[j][1]);
                den[j][1] = fmaf(WW.y, t1, den[j][1]);
            }
        }
        if (c + 1 < NC){ sts(buf ^ 1); __syncthreads(); buf ^= 1; }
    }

    // Combine halves: half 1 stores partials, half 0 adds them.
    __syncthreads();
    float* red = &sp[0][0][0][0][0];    // reuse SMEM (needs 2048 floats)
    if (hf == 1){
        #pragma unroll
        for (int j = 0; j < 4; j++){
            #pragma unroll
            for (int k = 0; k < 2; k++){
                red[txh*16 + j*2 + k]     = num[j][k];
                red[txh*16 + j*2 + k + 8] = den[j][k];
            }
        }
    }
    __syncthreads();
    if (hf == 0){
        #pragma unroll
        for (int j = 0; j < 4; j++){
            #pragma unroll
            for (int k = 0; k < 2; k++){
                num[j][k] += red[txh*16 + j*2 + k];
                den[j][k] += red[txh*16 + j*2 + k + 8];
            }
        }
    }
}

// ---------------------------------------------------------------------------
// Sensory pass: writes A[b,h], Dc[b,h] with all constants folded in.
// ---------------------------------------------------------------------------
__global__ __launch_bounds__(256) void k_sensory(
        const float* __restrict__ inp,
        const float* __restrict__ vleak, const float* __restrict__ gleak,
        const float* __restrict__ cm){
    __shared__ __align__(16) float sp[2][2][4][ICH][64];
    __shared__ float vs[2][2][16][ICH+1];

    const int h0 = blockIdx.x * 64;
    const int b0 = blockIdx.y * 16;
    const int tx = threadIdx.x;

    float num[4][2] = {}, den[4][2] = {};
    mainloop_core<I_SZ/2, I_SZ>(s_SG, s_MS, s_WE, s_WW, inp, h0, b0, tx,
                                num, den, sp, vs);

    if (tx < 128){
        const int lane = tx & 31;
        const int wq   = tx >> 5;
        #pragma unroll
        for (int k = 0; k < 2; k++){
            int h = h0 + 2*lane + k;
            float base_n = fmaf(gleak[h], vleak[h], g_CN[h]);
            float base_d = cm[h] + gleak[h] + g_CD[h];
            #pragma unroll
            for (int j = 0; j < 4; j++){
                int b = b0 + 4*wq + j;
                g_A [b*H_SZ + h] = num[j][k] + base_n;
                g_Dc[b*H_SZ + h] = den[j][k] + base_d;
            }
        }
    }
}

// ---------------------------------------------------------------------------
// One recurrent unfold.
// ---------------------------------------------------------------------------
__global__ __launch_bounds__(256) void k_step(const float* vext, float* voutext,
                                              int sel_in, int sel_out,
                                              const float* __restrict__ cm){
    const float* vin  = (sel_in  == 0) ? g_v0 : ((sel_in  == 1) ? g_v1 : vext);
    float*       vout = (sel_out == 0) ? g_v0 : ((sel_out == 1) ? g_v1 : voutext);

    __shared__ __align__(16) float sp[2][2][4][ICH][64];
    __shared__ float vs[2][2][16][ICH+1];

    const int h0 = blockIdx.x * 64;
    const int b0 = blockIdx.y * 16;
    const int tx = threadIdx.x;

    float num[4][2] = {}, den[4][2] = {};
    mainloop_core<H_SZ/2, H_SZ>(g_SG, g_MS, g_WE, g_WW, vin, h0, b0, tx,
                                num, den, sp, vs);

    if (tx < 128){
        const int lane = tx & 31;
        const int wq   = tx >> 5;
        #pragma unroll
        for (int k = 0; k < 2; k++){
            int h = h0 + 2*lane + k;
            float cmh = cm[h];
            #pragma unroll
            for (int j = 0; j < 4; j++){
                int b = b0 + 4*wq + j;
                float n = fmaf(cmh, vin[b*H_SZ + h], g_A[b*H_SZ + h]) + num[j][k];
                float d = g_Dc[b*H_SZ + h] + den[j][k];
                vout[b*H_SZ + h] = __fdividef(n, d + 1e-8f);
            }
        }
    }
}

extern "C" void kernel_launch(void* const* d_in, const int* in_sizes, int n_in,
                              void* d_out, int out_size){
    const float* inputs = (const float*)d_in[0];
    const float* state  = (const float*)d_in[1];
    const float* smu    = (const float*)d_in[2];
    const float* ssig   = (const float*)d_in[3];
    const float* sW     = (const float*)d_in[4];
    const float* serev  = (const float*)d_in[5];
    const float* mu     = (const float*)d_in[6];
    const float* sigma  = (const float*)d_in[7];
    const float* W      = (const float*)d_in[8];
    const float* erev   = (const float*)d_in[9];
    const float* vleak  = (const float*)d_in[10];
    const float* gleak  = (const float*)d_in[11];
    const float* cm     = (const float*)d_in[12];
    float* out = (float*)d_out;

    k_prep<<<((H_SZ+I_SZ)*H_SZ + 255)/256, 256>>>(mu, sigma, W, erev,
                                                  smu, ssig, sW, serev);
    k_colsum<<<H_SZ/32, 256>>>();

    dim3 grid(H_SZ/64, B_SZ/16);   // (8, 32) = 256 blocks, 256 threads each
    k_sensory<<<grid, 256>>>(inputs, vleak, gleak, cm);

    // 6 unfolds: state -> v0 -> v1 -> v0 -> v1 -> v0 -> out
    k_step<<<grid, 256>>>(state,   nullptr, 2, 0, cm);
    k_step<<<grid, 256>>>(nullptr, nullptr, 0, 1, cm);
    k_step<<<grid, 256>>>(nullptr, nullptr, 1, 0, cm);
    k_step<<<grid, 256>>>(nullptr, nullptr, 0, 1, cm);
    k_step<<<grid, 256>>>(nullptr, nullptr, 1, 0, cm);
    k_step<<<grid, 256>>>(nullptr, out,     0, 2, cm);
}